// round 1
// baseline (speedup 1.0000x reference)
#include <cuda_runtime.h>
#include <math.h>

#define HIDDEN   2048
#define NQ       8
#define HD       256
#define QKV_ROWS 2560   // (8 + 2) * 256
#define SEQ      8192
#define LAYER    5
#define NCHUNK   64
#define CHUNK    128    // SEQ / NCHUNK

// ---------------- scratch (device globals; no allocation) ----------------
__device__ float g_qkv[QKV_ROWS];        // raw qkv projection
__device__ float g_q[NQ * HD];           // normalized+rope+scaled Q
__device__ float g_k[HD];                // normalized+rope K (the new cache row)
__device__ float g_scores[NQ * SEQ];     // scores, then probs in-place
__device__ float g_part[NCHUNK * NQ * HD];
__device__ float g_attn[NQ * HD];

__device__ __forceinline__ float warp_sum(float v) {
#pragma unroll
    for (int o = 16; o; o >>= 1) v += __shfl_xor_sync(0xffffffffu, v, o);
    return v;
}

// ---------------- GEMV: y[r] = W[r, :HIDDEN] . x  (warp per row) ----------
__global__ void gemv_kernel(const float* __restrict__ W,
                            const float* __restrict__ x,
                            float* __restrict__ y, int rows) {
    __shared__ float sx[HIDDEN];
    int tid = threadIdx.x;
    for (int i = tid; i < HIDDEN; i += 256) sx[i] = x[i];
    __syncthreads();
    int warp = tid >> 5, lane = tid & 31;
    int row = blockIdx.x * 8 + warp;
    if (row >= rows) return;
    const float4* Wr  = reinterpret_cast<const float4*>(W + (size_t)row * HIDDEN);
    const float4* xs4 = reinterpret_cast<const float4*>(sx);
    float acc = 0.f;
#pragma unroll 16
    for (int i = lane; i < HIDDEN / 4; i += 32) {
        float4 w = Wr[i];
        float4 v = xs4[i];
        acc += w.x * v.x + w.y * v.y + w.z * v.z + w.w * v.w;
    }
    acc = warp_sum(acc);
    if (lane == 0) y[row] = acc;
}

// ---------------- per-head ANE-RMSNorm + RoPE ------------------------------
// blockIdx.x = head: 0..7 -> Q heads, 8 -> K head. 256 threads = HD dims.
__global__ void norm_rope_kernel(const float* __restrict__ cosv,
                                 const float* __restrict__ sinv,
                                 const float* __restrict__ qw,
                                 const float* __restrict__ kw) {
    int head = blockIdx.x;
    int d = threadIdx.x;
    __shared__ float red[256];
    __shared__ float ys[256];

    float x = g_qkv[head * HD + d];

    // maxval = max(|x|) clipped to 2^-24
    red[d] = fabsf(x);
    __syncthreads();
    for (int s = 128; s; s >>= 1) {
        if (d < s) red[d] = fmaxf(red[d], red[d + s]);
        __syncthreads();
    }
    float mv = fmaxf(red[0], 5.9604644775390625e-8f);
    __syncthreads();

    float xs = x / mv;
    red[d] = xs * xs;
    __syncthreads();
    for (int s = 128; s; s >>= 1) {
        if (d < s) red[d] += red[d + s];
        __syncthreads();
    }
    float rs = rsqrtf(red[0]);

    float w = (head < NQ) ? qw[d] : kw[d];
    float y = rs * 16.0f * xs * (1.0f + w);   // sqrt(256) = 16

    ys[d] = y;
    __syncthreads();
    float rot = (d < 128) ? -ys[d + 128] : ys[d - 128];
    float out = y * cosv[d] + rot * sinv[d];

    if (head < NQ) g_q[head * HD + d] = out * 0.0625f;  // 256^-0.5
    else           g_k[d] = out;
}

// ---------------- scores: softcap + mask, masked rows skipped --------------
__global__ void scores_kernel(const float* __restrict__ kc,
                              const float* __restrict__ mask,
                              const int* __restrict__ kvidx) {
    __shared__ float sq[NQ * HD];
    int tid = threadIdx.x;
    for (int i = tid; i < NQ * HD; i += 256) sq[i] = g_q[i];
    __syncthreads();

    int warp = tid >> 5, lane = tid & 31;
    int pos = *kvidx;
    const float* kbase = kc + (size_t)LAYER * SEQ * HD;

    for (int s = blockIdx.x * 8 + warp; s < SEQ; s += gridDim.x * 8) {
        float m = mask[s];
        if (m < -1e8f) {                       // masked: prob is exactly 0
            if (lane < NQ) g_scores[lane * SEQ + s] = -1e9f;
            continue;
        }
        const float* krow = (s == pos) ? g_k : (kbase + (size_t)s * HD);
        const float4* k4 = reinterpret_cast<const float4*>(krow);
        float acc[8] = {0, 0, 0, 0, 0, 0, 0, 0};
#pragma unroll
        for (int i = 0; i < 2; i++) {
            int idx = i * 32 + lane;           // 64 float4 per 256-dim row
            float4 kv = k4[idx];
#pragma unroll
            for (int h = 0; h < 8; h++) {
                const float4* q4 = reinterpret_cast<const float4*>(&sq[h * HD]);
                float4 qv = q4[idx];
                acc[h] += kv.x * qv.x + kv.y * qv.y + kv.z * qv.z + kv.w * qv.w;
            }
        }
#pragma unroll
        for (int h = 0; h < 8; h++) {
            float v = warp_sum(acc[h]);
            if (lane == h)
                g_scores[h * SEQ + s] = tanhf(v * 0.02f) * 50.0f + m;
        }
    }
}

// ---------------- per-head softmax over SEQ (probs in-place) --------------
__global__ void softmax_kernel() {
    int h = blockIdx.x;
    int tid = threadIdx.x;
    __shared__ float red[256];
    float* sc = g_scores + (size_t)h * SEQ;

    float mx = -1e30f;
    for (int i = tid; i < SEQ; i += 256) mx = fmaxf(mx, sc[i]);
    red[tid] = mx;
    __syncthreads();
    for (int s = 128; s; s >>= 1) {
        if (tid < s) red[tid] = fmaxf(red[tid], red[tid + s]);
        __syncthreads();
    }
    mx = red[0];
    __syncthreads();

    float sum = 0.f;
    for (int i = tid; i < SEQ; i += 256) {
        float e = expf(sc[i] - mx);            // masked -> exactly 0
        sc[i] = e;
        sum += e;
    }
    red[tid] = sum;
    __syncthreads();
    for (int s = 128; s; s >>= 1) {
        if (tid < s) red[tid] += red[tid + s];
        __syncthreads();
    }
    float inv = 1.0f / red[0];
    for (int i = tid; i < SEQ; i += 256) sc[i] *= inv;
}

// ---------------- P.V partials: block per 128-position chunk ---------------
__global__ void attnv_kernel(const float* __restrict__ vc,
                             const int* __restrict__ kvidx) {
    int c = blockIdx.x;
    int tid = threadIdx.x;                     // = dim d, 0..255
    __shared__ float sp[CHUNK * NQ];           // [s_local][h]
    __shared__ float spm[CHUNK];
    __shared__ float red[256];
    int s0 = c * CHUNK;

    float mx = 0.f;
    for (int idx = tid; idx < CHUNK * NQ; idx += 256) {
        int sl = idx >> 3, h = idx & 7;
        float p = g_scores[h * SEQ + s0 + sl];
        sp[sl * NQ + h] = p;
        mx = fmaxf(mx, p);
    }
    red[tid] = mx;
    __syncthreads();
    for (int s = 128; s; s >>= 1) {
        if (tid < s) red[tid] = fmaxf(red[tid], red[tid + s]);
        __syncthreads();
    }
    if (red[0] == 0.0f) {                      // whole chunk masked
#pragma unroll
        for (int h = 0; h < 8; h++) g_part[c * 2048 + h * 256 + tid] = 0.0f;
        return;
    }
    if (tid < CHUNK) {
        float m = 0.f;
#pragma unroll
        for (int h = 0; h < 8; h++) m = fmaxf(m, sp[tid * NQ + h]);
        spm[tid] = m;
    }
    __syncthreads();

    int pos = *kvidx;
    const float* vbase = vc + (size_t)LAYER * SEQ * HD;
    const float* vnew = g_qkv + 9 * HD;        // xv (head 9 of qkv projection)

    float acc[8] = {0, 0, 0, 0, 0, 0, 0, 0};
    for (int sl = 0; sl < CHUNK; sl++) {
        if (spm[sl] == 0.f) continue;          // row fully masked -> skip V load
        int s = s0 + sl;
        float v = (s == pos) ? vnew[tid] : vbase[(size_t)s * HD + tid];
#pragma unroll
        for (int h = 0; h < 8; h++) acc[h] += sp[sl * NQ + h] * v;
    }
#pragma unroll
    for (int h = 0; h < 8; h++) g_part[c * 2048 + h * 256 + tid] = acc[h];
}

// ---------------- reduce partials over chunks ------------------------------
__global__ void reduce_kernel() {
    int i = blockIdx.x * 256 + threadIdx.x;    // 0..2047 = h*256+d
    float s = 0.f;
    for (int c = 0; c < NCHUNK; c++) s += g_part[c * 2048 + i];
    g_attn[i] = s;
}

// ---------------- launch ----------------------------------------------------
extern "C" void kernel_launch(void* const* d_in, const int* in_sizes, int n_in,
                              void* d_out, int out_size) {
    const float* hs   = (const float*)d_in[0];   // hidden_states (2048)
    const float* cosv = (const float*)d_in[1];   // cos (256)
    const float* sinv = (const float*)d_in[2];   // sin (256)
    const int*   kvix = (const int*)  d_in[3];   // kv_write_indices (1)
    const float* kc   = (const float*)d_in[4];   // k_cache
    const float* vc   = (const float*)d_in[5];   // v_cache
    const float* mask = (const float*)d_in[6];   // mask (8192)
    const float* qkvw = (const float*)d_in[7];   // qkv_w (2560x2048)
    const float* ow   = (const float*)d_in[8];   // o_w   (2048x2048)
    const float* qnw  = (const float*)d_in[9];   // q_norm_w (256)
    const float* knw  = (const float*)d_in[10];  // k_norm_w (256)
    float* out = (float*)d_out;

    void* p_qkv = nullptr;
    void* p_attn = nullptr;
    cudaGetSymbolAddress(&p_qkv, g_qkv);
    cudaGetSymbolAddress(&p_attn, g_attn);

    gemv_kernel<<<QKV_ROWS / 8, 256>>>(qkvw, hs, (float*)p_qkv, QKV_ROWS);
    norm_rope_kernel<<<9, 256>>>(cosv, sinv, qnw, knw);
    scores_kernel<<<128, 256>>>(kc, mask, kvix);
    softmax_kernel<<<NQ, 256>>>();
    attnv_kernel<<<NCHUNK, 256>>>(vc, kvix);
    reduce_kernel<<<NQ, 256>>>();
    gemv_kernel<<<HIDDEN / 8, 256>>>(ow, (const float*)p_attn, out, HIDDEN);
}

// round 2
// speedup vs baseline: 1.5121x; 1.5121x over previous
#include <cuda_runtime.h>
#include <math.h>

#define HIDDEN   2048
#define NQ       8
#define HD       256
#define QKV_ROWS 2560   // (8 + 2) * 256
#define SEQ      8192
#define LAYER    5
#define CHUNK    64
#define NCHUNK   128    // SEQ / CHUNK

// ---------------- scratch (device globals; no allocation) ----------------
__device__ float g_qkv[QKV_ROWS];              // raw qkv projection
__device__ float g_part[NCHUNK * NQ * HD];     // per-chunk partial P.V (unnormalized)
__device__ float g_l[NCHUNK * NQ];             // per-chunk exp-sums
__device__ float g_attn[NQ * HD];              // combined attention output

__device__ __forceinline__ float warp_sum(float v) {
#pragma unroll
    for (int o = 16; o; o >>= 1) v += __shfl_xor_sync(0xffffffffu, v, o);
    return v;
}
__device__ __forceinline__ float warp_max(float v) {
#pragma unroll
    for (int o = 16; o; o >>= 1) v = fmaxf(v, __shfl_xor_sync(0xffffffffu, v, o));
    return v;
}

// ---------------- GEMV: y[r] = W[r, :HIDDEN] . x  (warp per row) ----------
__global__ void gemv_kernel(const float* __restrict__ W,
                            const float* __restrict__ x,
                            float* __restrict__ y, int rows) {
    __shared__ float sx[HIDDEN];
    int tid = threadIdx.x;
    for (int i = tid; i < HIDDEN; i += 256) sx[i] = x[i];
    __syncthreads();
    int warp = tid >> 5, lane = tid & 31;
    int row = blockIdx.x * 8 + warp;
    if (row >= rows) return;
    const float4* Wr  = reinterpret_cast<const float4*>(W + (size_t)row * HIDDEN);
    const float4* xs4 = reinterpret_cast<const float4*>(sx);
    float acc = 0.f;
#pragma unroll 16
    for (int i = lane; i < HIDDEN / 4; i += 32) {
        float4 w = Wr[i];
        float4 v = xs4[i];
        acc += w.x * v.x + w.y * v.y + w.z * v.z + w.w * v.w;
    }
    acc = warp_sum(acc);
    if (lane == 0) y[row] = acc;
}

// ---------------- fused attention: norm+rope + scores + exp + partial PV ---
// grid = NCHUNK blocks of 256 threads; block c handles positions
// [c*CHUNK, (c+1)*CHUNK). Because softcap bounds scores to [-50,50],
// exp never overflows -> no running max needed (one-pass flash decode).
__global__ void fused_attn_kernel(const float* __restrict__ kc,
                                  const float* __restrict__ vc,
                                  const float* __restrict__ mask,
                                  const float* __restrict__ cosv,
                                  const float* __restrict__ sinv,
                                  const float* __restrict__ qw,
                                  const float* __restrict__ kw,
                                  const int* __restrict__ kvidx) {
    __shared__ float sq[NQ * HD];      // normalized+rope+scaled Q, head-major
    __shared__ float sk[HD];           // normalized+rope K (the new cache row)
    __shared__ float sexp[CHUNK * NQ]; // exp'd scores [sl][h]
    __shared__ float smask[CHUNK];
    __shared__ int   sany;

    int c   = blockIdx.x;
    int tid = threadIdx.x;
    int warp = tid >> 5, lane = tid & 31;
    int s0 = c * CHUNK;

    // --- phase 0: mask check; fully-masked chunks exit immediately --------
    if (tid == 0) sany = 0;
    __syncthreads();
    if (tid < CHUNK) {
        float m = mask[s0 + tid];
        smask[tid] = m;
        if (m > -1e8f) atomicOr(&sany, 1);   // shared-mem atomic: fine
    }
    __syncthreads();
    if (!sany) {
        if (tid < NQ) g_l[c * NQ + tid] = 0.0f;
        return;
    }

    // --- phase 1: norm + rope (redundant per block; tiny, L2-resident) ----
    // warp w handles heads w, w+8 (head 8 = K head). dim mapping:
    // d = lane + 32*j, j in [0,8). Partner for rotate_half is j^4, same lane.
    for (int head = warp; head < 9; head += 8) {
        float x[8];
#pragma unroll
        for (int j = 0; j < 8; j++) x[j] = g_qkv[head * HD + lane + 32 * j];
        float mv = 0.f;
#pragma unroll
        for (int j = 0; j < 8; j++) mv = fmaxf(mv, fabsf(x[j]));
        mv = warp_max(mv);
        mv = fmaxf(mv, 5.9604644775390625e-8f);   // 2^-24
        float ss = 0.f;
        float xs[8];
#pragma unroll
        for (int j = 0; j < 8; j++) { xs[j] = x[j] / mv; ss += xs[j] * xs[j]; }
        ss = warp_sum(ss);
        float rs = rsqrtf(ss);
        const float* wv = (head < NQ) ? qw : kw;
        float y[8];
#pragma unroll
        for (int j = 0; j < 8; j++) {
            int d = lane + 32 * j;
            y[j] = rs * 16.0f * xs[j] * (1.0f + wv[d]);
        }
#pragma unroll
        for (int j = 0; j < 8; j++) {
            int d = lane + 32 * j;
            float rot = (j < 4) ? -y[j ^ 4] : y[j ^ 4];
            float out = y[j] * cosv[d] + rot * sinv[d];
            if (head < NQ) sq[head * HD + d] = out * 0.0625f;  // * 256^-0.5
            else           sk[d] = out;
        }
    }
    __syncthreads();

    int pos = *kvidx;
    const float* kbase = kc + (size_t)LAYER * SEQ * HD;

    // --- phase 2: scores -> softcap -> exp (warp per 8 positions) ---------
#pragma unroll
    for (int r = 0; r < CHUNK / 8; r++) {
        int sl = warp * (CHUNK / 8) + r;
        int s = s0 + sl;
        float m = smask[sl];
        if (m < -1e8f) {
            if (lane < NQ) sexp[sl * NQ + lane] = 0.0f;
            continue;
        }
        const float* krow = (s == pos) ? sk : (kbase + (size_t)s * HD);
        const float4* k4 = reinterpret_cast<const float4*>(krow);
        float acc[NQ] = {0, 0, 0, 0, 0, 0, 0, 0};
#pragma unroll
        for (int i = 0; i < 2; i++) {
            int idx = i * 32 + lane;
            float4 kv = k4[idx];
#pragma unroll
            for (int h = 0; h < NQ; h++) {
                const float4* q4 = reinterpret_cast<const float4*>(&sq[h * HD]);
                float4 qv = q4[idx];
                acc[h] += kv.x * qv.x + kv.y * qv.y + kv.z * qv.z + kv.w * qv.w;
            }
        }
#pragma unroll
        for (int h = 0; h < NQ; h++) {
            float v = warp_sum(acc[h]);
            if (lane == h)
                sexp[sl * NQ + h] = expf(tanhf(v * 0.02f) * 50.0f + m);
        }
    }
    __syncthreads();

    // --- phase 3: per-head exp-sum (warp h reduces column h) --------------
    if (warp < NQ) {
        int h = warp;
        float l = sexp[lane * NQ + h] + sexp[(lane + 32) * NQ + h];
        l = warp_sum(l);
        if (lane == 0) g_l[c * NQ + h] = l;
    }

    // --- phase 4: partial P.V (thread = dim d) -----------------------------
    const float* vbase = vc + (size_t)LAYER * SEQ * HD;
    const float* vnew  = g_qkv + 9 * HD;     // xv row of qkv projection
    int d = tid;
    float acc[NQ] = {0, 0, 0, 0, 0, 0, 0, 0};
#pragma unroll 4
    for (int sl = 0; sl < CHUNK; sl++) {
        int s = s0 + sl;
        float v = (s == pos) ? vnew[d] : vbase[(size_t)s * HD + d];
#pragma unroll
        for (int h = 0; h < NQ; h++) acc[h] += sexp[sl * NQ + h] * v;
    }
#pragma unroll
    for (int h = 0; h < NQ; h++)
        g_part[(c * NQ + h) * HD + d] = acc[h];
}

// ---------------- combine partials across chunks ---------------------------
__global__ void combine_kernel() {
    int h = blockIdx.x;
    int d = threadIdx.x;
    __shared__ float sl[NCHUNK];
    if (d < NCHUNK) sl[d] = g_l[d * NQ + h];
    __syncthreads();
    float L = 0.f, acc = 0.f;
    for (int c = 0; c < NCHUNK; c++) {
        float l = sl[c];
        if (l > 0.f) {
            L += l;
            acc += g_part[(c * NQ + h) * HD + d];
        }
    }
    g_attn[h * HD + d] = acc / L;
}

// ---------------- launch ----------------------------------------------------
extern "C" void kernel_launch(void* const* d_in, const int* in_sizes, int n_in,
                              void* d_out, int out_size) {
    const float* hs   = (const float*)d_in[0];   // hidden_states (2048)
    const float* cosv = (const float*)d_in[1];   // cos (256)
    const float* sinv = (const float*)d_in[2];   // sin (256)
    const int*   kvix = (const int*)  d_in[3];   // kv_write_indices (1)
    const float* kc   = (const float*)d_in[4];   // k_cache
    const float* vc   = (const float*)d_in[5];   // v_cache
    const float* mask = (const float*)d_in[6];   // mask (8192)
    const float* qkvw = (const float*)d_in[7];   // qkv_w (2560x2048)
    const float* ow   = (const float*)d_in[8];   // o_w   (2048x2048)
    const float* qnw  = (const float*)d_in[9];   // q_norm_w (256)
    const float* knw  = (const float*)d_in[10];  // k_norm_w (256)
    float* out = (float*)d_out;

    void* p_qkv = nullptr;
    void* p_attn = nullptr;
    cudaGetSymbolAddress(&p_qkv, g_qkv);
    cudaGetSymbolAddress(&p_attn, g_attn);

    gemv_kernel<<<QKV_ROWS / 8, 256>>>(qkvw, hs, (float*)p_qkv, QKV_ROWS);
    fused_attn_kernel<<<NCHUNK, 256>>>(kc, vc, mask, cosv, sinv, qnw, knw, kvix);
    combine_kernel<<<NQ, 256>>>();
    gemv_kernel<<<HIDDEN / 8, 256>>>(ow, (const float*)p_attn, out, HIDDEN);
}

// round 3
// speedup vs baseline: 2.0526x; 1.3575x over previous
#include <cuda_runtime.h>
#include <math.h>

#define HIDDEN   2048
#define NQ       8
#define HD       256
#define QKV_ROWS 2560   // (8 + 2) * 256
#define SEQ      8192
#define LAYER    5
#define CHUNK    32
#define NCHUNK   256    // SEQ / CHUNK
#define RPB      4      // gemv rows per block

// ---------------- scratch (device globals; no allocation) ----------------
__device__ float g_qkv[QKV_ROWS];              // raw qkv projection
__device__ float g_part[NCHUNK * NQ * HD];     // per-chunk partial P.V
__device__ float g_l[NCHUNK * NQ];             // per-chunk exp-sums
__device__ float g_attn[NQ * HD];              // combined attention output

__device__ __forceinline__ float warp_sum(float v) {
#pragma unroll
    for (int o = 16; o; o >>= 1) v += __shfl_xor_sync(0xffffffffu, v, o);
    return v;
}
__device__ __forceinline__ float warp_max(float v) {
#pragma unroll
    for (int o = 16; o; o >>= 1) v = fmaxf(v, __shfl_xor_sync(0xffffffffu, v, o));
    return v;
}

// ---------------- GEMV: 4 rows/block, 64 threads/row, 8 float4/thread ------
__global__ void gemv_kernel(const float* __restrict__ W,
                            const float* __restrict__ x,
                            float* __restrict__ y) {
    __shared__ float4 sx[HIDDEN / 4];
    __shared__ float swarp[8];
    int tid = threadIdx.x;
    const float4* x4 = reinterpret_cast<const float4*>(x);
    sx[tid]       = x4[tid];
    sx[tid + 256] = x4[tid + 256];
    __syncthreads();

    int rl  = tid >> 6;          // row within block (0..3)
    int t64 = tid & 63;
    int row = blockIdx.x * RPB + rl;
    const float4* Wr = reinterpret_cast<const float4*>(W + (size_t)row * HIDDEN);

    float acc = 0.f;
#pragma unroll
    for (int i = 0; i < 8; i++) {
        float4 w = Wr[t64 + 64 * i];     // 8 independent 16B loads in flight
        float4 v = sx[t64 + 64 * i];
        acc += w.x * v.x + w.y * v.y + w.z * v.z + w.w * v.w;
    }
    acc = warp_sum(acc);
    int warp = tid >> 5, lane = tid & 31;
    if (lane == 0) swarp[warp] = acc;
    __syncthreads();
    if (tid < RPB)
        y[blockIdx.x * RPB + tid] = swarp[2 * tid] + swarp[2 * tid + 1];
}

// ---------------- fused attention: norm+rope + scores + exp + partial PV ---
// One-pass flash decode: softcap bounds scores to [-50,50] so exp never
// overflows -> no running max needed. Block c owns positions [c*32,(c+1)*32).
__global__ void fused_attn_kernel(const float* __restrict__ kc,
                                  const float* __restrict__ vc,
                                  const float* __restrict__ mask,
                                  const float* __restrict__ cosv,
                                  const float* __restrict__ sinv,
                                  const float* __restrict__ qw,
                                  const float* __restrict__ kw,
                                  const int* __restrict__ kvidx) {
    __shared__ float sq[NQ * HD];      // normalized+rope+scaled Q, head-major
    __shared__ float sk[HD];           // normalized+rope K (new cache row)
    __shared__ float sexp[CHUNK * NQ]; // exp'd scores [sl][h]
    __shared__ float smask[CHUNK];
    __shared__ int   sany;

    int c    = blockIdx.x;
    int tid  = threadIdx.x;
    int warp = tid >> 5, lane = tid & 31;
    int s0   = c * CHUNK;

    // --- phase 0: fully-masked chunks exit immediately --------------------
    if (tid == 0) sany = 0;
    __syncthreads();
    if (tid < CHUNK) {
        float m = mask[s0 + tid];
        smask[tid] = m;
        if (m > -1e8f) atomicOr(&sany, 1);
    }
    __syncthreads();
    if (!sany) {
        if (tid < NQ) g_l[c * NQ + tid] = 0.0f;
        return;
    }

    // --- phase 1: norm + rope (recomputed per block; L2-resident, tiny) ---
    for (int head = warp; head < 9; head += 8) {
        float x[8];
#pragma unroll
        for (int j = 0; j < 8; j++) x[j] = g_qkv[head * HD + lane + 32 * j];
        float mv = 0.f;
#pragma unroll
        for (int j = 0; j < 8; j++) mv = fmaxf(mv, fabsf(x[j]));
        mv = warp_max(mv);
        mv = fmaxf(mv, 5.9604644775390625e-8f);   // 2^-24
        float ss = 0.f, xs[8];
#pragma unroll
        for (int j = 0; j < 8; j++) { xs[j] = x[j] / mv; ss += xs[j] * xs[j]; }
        ss = warp_sum(ss);
        float rs = rsqrtf(ss);
        const float* wv = (head < NQ) ? qw : kw;
        float y[8];
#pragma unroll
        for (int j = 0; j < 8; j++) {
            int d = lane + 32 * j;
            y[j] = rs * 16.0f * xs[j] * (1.0f + wv[d]);
        }
#pragma unroll
        for (int j = 0; j < 8; j++) {
            int d = lane + 32 * j;
            float rot = (j < 4) ? -y[j ^ 4] : y[j ^ 4];
            float out = y[j] * cosv[d] + rot * sinv[d];
            if (head < NQ) sq[head * HD + d] = out * 0.0625f;  // * 256^-0.5
            else           sk[d] = out;
        }
    }
    __syncthreads();

    int pos = *kvidx;
    const float* kbase = kc + (size_t)LAYER * SEQ * HD;

    // --- phase 2: scores -> softcap -> exp (warp per 4 positions) ---------
#pragma unroll
    for (int r = 0; r < CHUNK / 8; r++) {
        int sl = warp * (CHUNK / 8) + r;
        int s = s0 + sl;
        float m = smask[sl];
        if (m < -1e8f) {
            if (lane < NQ) sexp[sl * NQ + lane] = 0.0f;
            continue;
        }
        const float* krow = (s == pos) ? sk : (kbase + (size_t)s * HD);
        const float4* k4 = reinterpret_cast<const float4*>(krow);
        float acc[NQ] = {0, 0, 0, 0, 0, 0, 0, 0};
#pragma unroll
        for (int i = 0; i < 2; i++) {
            int idx = i * 32 + lane;
            float4 kv = k4[idx];
#pragma unroll
            for (int h = 0; h < NQ; h++) {
                const float4* q4 = reinterpret_cast<const float4*>(&sq[h * HD]);
                float4 qv = q4[idx];
                acc[h] += kv.x * qv.x + kv.y * qv.y + kv.z * qv.z + kv.w * qv.w;
            }
        }
#pragma unroll
        for (int h = 0; h < NQ; h++) {
            float v = warp_sum(acc[h]);
            if (lane == h)
                sexp[sl * NQ + h] = expf(tanhf(v * 0.02f) * 50.0f + m);
        }
    }
    __syncthreads();

    // --- phase 3: per-head exp-sum (warp h reduces column h) --------------
    if (warp < NQ) {
        int h = warp;
        float l = sexp[lane * NQ + h];         // CHUNK == 32 rows
        l = warp_sum(l);
        if (lane == 0) g_l[c * NQ + h] = l;
    }

    // --- phase 4: partial P.V (thread = dim d), deep unroll for MLP -------
    const float* vbase = vc + (size_t)LAYER * SEQ * HD;
    const float* vnew  = g_qkv + 9 * HD;       // xv row of qkv projection
    int d = tid;
    float acc[NQ] = {0, 0, 0, 0, 0, 0, 0, 0};
#pragma unroll 8
    for (int sl = 0; sl < CHUNK; sl++) {
        int s = s0 + sl;
        float v = (s == pos) ? vnew[d] : vbase[(size_t)s * HD + d];
#pragma unroll
        for (int h = 0; h < NQ; h++) acc[h] += sexp[sl * NQ + h] * v;
    }
#pragma unroll
    for (int h = 0; h < NQ; h++)
        g_part[(c * NQ + h) * HD + d] = acc[h];
}

// ---------------- combine partials across chunks ---------------------------
// grid = (NQ, 4): block (h, slice) covers 64 d-values; 4 threads per output
// each summing a strided quarter of the chunks.
__global__ void combine_kernel() {
    int h  = blockIdx.x;
    int d0 = blockIdx.y * 64;
    int tid = threadIdx.x;
    int q = tid >> 6, dl = tid & 63;
    int d = d0 + dl;

    float acc = 0.f, L = 0.f;
#pragma unroll 8
    for (int k = 0; k < NCHUNK / 4; k++) {
        int c = q + 4 * k;
        float l = g_l[c * NQ + h];
        if (l > 0.f) {
            L += l;
            acc += g_part[(c * NQ + h) * HD + d];
        }
    }
    __shared__ float sacc[4][64];
    __shared__ float sL[4][64];
    sacc[q][dl] = acc;
    sL[q][dl]   = L;
    __syncthreads();
    if (q == 0) {
        acc = sacc[0][dl] + sacc[1][dl] + sacc[2][dl] + sacc[3][dl];
        L   = sL[0][dl] + sL[1][dl] + sL[2][dl] + sL[3][dl];
        g_attn[h * HD + d] = acc / L;
    }
}

// ---------------- launch ----------------------------------------------------
extern "C" void kernel_launch(void* const* d_in, const int* in_sizes, int n_in,
                              void* d_out, int out_size) {
    const float* hs   = (const float*)d_in[0];   // hidden_states (2048)
    const float* cosv = (const float*)d_in[1];   // cos (256)
    const float* sinv = (const float*)d_in[2];   // sin (256)
    const int*   kvix = (const int*)  d_in[3];   // kv_write_indices (1)
    const float* kc   = (const float*)d_in[4];   // k_cache
    const float* vc   = (const float*)d_in[5];   // v_cache
    const float* mask = (const float*)d_in[6];   // mask (8192)
    const float* qkvw = (const float*)d_in[7];   // qkv_w (2560x2048)
    const float* ow   = (const float*)d_in[8];   // o_w   (2048x2048)
    const float* qnw  = (const float*)d_in[9];   // q_norm_w (256)
    const float* knw  = (const float*)d_in[10];  // k_norm_w (256)
    float* out = (float*)d_out;

    void* p_qkv = nullptr;
    void* p_attn = nullptr;
    cudaGetSymbolAddress(&p_qkv, g_qkv);
    cudaGetSymbolAddress(&p_attn, g_attn);

    gemv_kernel<<<QKV_ROWS / RPB, 256>>>(qkvw, hs, (float*)p_qkv);
    fused_attn_kernel<<<NCHUNK, 256>>>(kc, vc, mask, cosv, sinv, qnw, knw, kvix);
    combine_kernel<<<dim3(NQ, 4), 256>>>();
    gemv_kernel<<<HIDDEN / RPB, 256>>>(ow, (const float*)p_attn, out);
}

// round 4
// speedup vs baseline: 2.2102x; 1.0767x over previous
#include <cuda_runtime.h>
#include <math.h>

#define HIDDEN   2048
#define NQ       8
#define HD       256
#define QKV_ROWS 2560   // (8 + 2) * 256
#define SEQ      8192
#define LAYER    5
#define CHUNK    32
#define NCHUNK   256    // SEQ / CHUNK

// ---------------- scratch (device globals; no allocation) ----------------
__device__ float g_qkv[QKV_ROWS];              // raw qkv projection
__device__ float g_part[NCHUNK * NQ * HD];     // per-chunk partial P.V
__device__ float g_l[NCHUNK * NQ];             // per-chunk exp-sums
__device__ float g_attn[NQ * HD];              // combined attention output

__device__ __forceinline__ float warp_sum(float v) {
#pragma unroll
    for (int o = 16; o; o >>= 1) v += __shfl_xor_sync(0xffffffffu, v, o);
    return v;
}
__device__ __forceinline__ float warp_max(float v) {
#pragma unroll
    for (int o = 16; o; o >>= 1) v = fmaxf(v, __shfl_xor_sync(0xffffffffu, v, o));
    return v;
}

// ---------------- GEMV: 2 rows/block, 128 threads/row, 4 float4/thread -----
// x read straight from global (L2-hot, shared via L1 between the 2 rows);
// no smem staging sync -> W and x loads form one front-batched LDG burst.
__global__ void gemv_kernel(const float* __restrict__ W,
                            const float* __restrict__ x,
                            float* __restrict__ y) {
    int tid = threadIdx.x;
    int rl  = tid >> 7;            // row within block (0..1)
    int t   = tid & 127;           // thread within row
    int row = blockIdx.x * 2 + rl;
    const float4* Wr = reinterpret_cast<const float4*>(W + (size_t)row * HIDDEN);
    const float4* x4 = reinterpret_cast<const float4*>(x);

    float4 w0 = Wr[t];
    float4 w1 = Wr[t + 128];
    float4 w2 = Wr[t + 256];
    float4 w3 = Wr[t + 384];
    float4 v0 = __ldg(&x4[t]);
    float4 v1 = __ldg(&x4[t + 128]);
    float4 v2 = __ldg(&x4[t + 256]);
    float4 v3 = __ldg(&x4[t + 384]);

    float acc = w0.x * v0.x + w0.y * v0.y + w0.z * v0.z + w0.w * v0.w;
    acc += w1.x * v1.x + w1.y * v1.y + w1.z * v1.z + w1.w * v1.w;
    acc += w2.x * v2.x + w2.y * v2.y + w2.z * v2.z + w2.w * v2.w;
    acc += w3.x * v3.x + w3.y * v3.y + w3.z * v3.z + w3.w * v3.w;

    acc = warp_sum(acc);
    __shared__ float swarp[8];
    int warp = tid >> 5, lane = tid & 31;
    if (lane == 0) swarp[warp] = acc;
    __syncthreads();
    if (tid < 2) {
        float r = swarp[4 * tid] + swarp[4 * tid + 1] +
                  swarp[4 * tid + 2] + swarp[4 * tid + 3];
        y[blockIdx.x * 2 + tid] = r;
    }
}

// ---------------- fused attention: norm+rope + scores + exp + partial PV ---
// One-pass flash decode: softcap bounds scores to [-50,50] so exp never
// overflows -> no running max needed. Block c owns positions [c*32,(c+1)*32).
__global__ void fused_attn_kernel(const float* __restrict__ kc,
                                  const float* __restrict__ vc,
                                  const float* __restrict__ mask,
                                  const float* __restrict__ cosv,
                                  const float* __restrict__ sinv,
                                  const float* __restrict__ qw,
                                  const float* __restrict__ kw,
                                  const int* __restrict__ kvidx) {
    __shared__ float sq[NQ * HD];      // normalized+rope+scaled Q, head-major
    __shared__ float sk[HD];           // normalized+rope K (new cache row)
    __shared__ float sexp[CHUNK * NQ]; // exp'd scores [sl][h]
    __shared__ float smask[CHUNK];
    __shared__ int   sany;

    int c    = blockIdx.x;
    int tid  = threadIdx.x;
    int warp = tid >> 5, lane = tid & 31;
    int s0   = c * CHUNK;

    // --- phase 0: fully-masked chunks exit immediately --------------------
    if (tid == 0) sany = 0;
    __syncthreads();
    if (tid < CHUNK) {
        float m = mask[s0 + tid];
        smask[tid] = m;
        if (m > -1e8f) atomicOr(&sany, 1);
    }
    __syncthreads();
    if (!sany) {
        if (tid < NQ) g_l[c * NQ + tid] = 0.0f;
        return;
    }

    // --- phase 1: norm + rope (recomputed per block; L2-resident, tiny) ---
    for (int head = warp; head < 9; head += 8) {
        float x[8];
#pragma unroll
        for (int j = 0; j < 8; j++) x[j] = g_qkv[head * HD + lane + 32 * j];
        float mv = 0.f;
#pragma unroll
        for (int j = 0; j < 8; j++) mv = fmaxf(mv, fabsf(x[j]));
        mv = warp_max(mv);
        mv = fmaxf(mv, 5.9604644775390625e-8f);   // 2^-24
        float ss = 0.f, xs[8];
#pragma unroll
        for (int j = 0; j < 8; j++) { xs[j] = x[j] / mv; ss += xs[j] * xs[j]; }
        ss = warp_sum(ss);
        float rs = rsqrtf(ss);
        const float* wv = (head < NQ) ? qw : kw;
        float y[8];
#pragma unroll
        for (int j = 0; j < 8; j++) {
            int d = lane + 32 * j;
            y[j] = rs * 16.0f * xs[j] * (1.0f + wv[d]);
        }
#pragma unroll
        for (int j = 0; j < 8; j++) {
            int d = lane + 32 * j;
            float rot = (j < 4) ? -y[j ^ 4] : y[j ^ 4];
            float out = y[j] * cosv[d] + rot * sinv[d];
            if (head < NQ) sq[head * HD + d] = out * 0.0625f;  // * 256^-0.5
            else           sk[d] = out;
        }
    }
    __syncthreads();

    int pos = *kvidx;
    const float* kbase = kc + (size_t)LAYER * SEQ * HD;

    // --- phase 2: scores -> softcap -> exp (warp per 4 positions) ---------
    {
        float acc[4][NQ];
        const float4* k4p[4];
#pragma unroll
        for (int r = 0; r < 4; r++) {
            int sl = warp * 4 + r;
            int s = s0 + sl;
            const float* krow = (s == pos) ? sk : (kbase + (size_t)s * HD);
            k4p[r] = reinterpret_cast<const float4*>(krow);
#pragma unroll
            for (int h = 0; h < NQ; h++) acc[r][h] = 0.f;
        }
        // front-batch all 8 K loads (2 per position x 4 positions)
#pragma unroll
        for (int i = 0; i < 2; i++) {
            int idx = i * 32 + lane;
            float4 kv[4];
#pragma unroll
            for (int r = 0; r < 4; r++) kv[r] = k4p[r][idx];
#pragma unroll
            for (int h = 0; h < NQ; h++) {
                const float4* q4 = reinterpret_cast<const float4*>(&sq[h * HD]);
                float4 qv = q4[idx];
#pragma unroll
                for (int r = 0; r < 4; r++) {
                    acc[r][h] += kv[r].x * qv.x + kv[r].y * qv.y +
                                 kv[r].z * qv.z + kv[r].w * qv.w;
                }
            }
        }
#pragma unroll
        for (int r = 0; r < 4; r++) {
            int sl = warp * 4 + r;
            float m = smask[sl];
#pragma unroll
            for (int h = 0; h < NQ; h++) {
                float v = warp_sum(acc[r][h]);
                if (lane == h)
                    sexp[sl * NQ + h] = (m < -1e8f) ? 0.0f
                                      : expf(tanhf(v * 0.02f) * 50.0f + m);
            }
        }
    }
    __syncthreads();

    // --- phase 3: per-head exp-sum (warp h reduces column h) --------------
    if (warp < NQ) {
        int h = warp;
        float l = sexp[lane * NQ + h];         // CHUNK == 32 rows
        l = warp_sum(l);
        if (lane == 0) g_l[c * NQ + h] = l;
    }

    // --- phase 4: partial P.V (thread = dim d), deep unroll for MLP -------
    const float* vbase = vc + (size_t)LAYER * SEQ * HD;
    const float* vnew  = g_qkv + 9 * HD;       // xv row of qkv projection
    int d = tid;
    float acc[NQ] = {0, 0, 0, 0, 0, 0, 0, 0};
#pragma unroll 8
    for (int sl = 0; sl < CHUNK; sl++) {
        int s = s0 + sl;
        float v = (s == pos) ? vnew[d] : vbase[(size_t)s * HD + d];
#pragma unroll
        for (int h = 0; h < NQ; h++) acc[h] += sexp[sl * NQ + h] * v;
    }
#pragma unroll
    for (int h = 0; h < NQ; h++)
        g_part[(c * NQ + h) * HD + d] = acc[h];
}

// ---------------- combine partials across chunks ---------------------------
// grid = (NQ, 4): block (h, slice) covers 64 d-values; 4 threads per output
// each summing a strided quarter of the chunks.
__global__ void combine_kernel() {
    int h  = blockIdx.x;
    int d0 = blockIdx.y * 64;
    int tid = threadIdx.x;
    int q = tid >> 6, dl = tid & 63;
    int d = d0 + dl;

    float acc = 0.f, L = 0.f;
#pragma unroll 8
    for (int k = 0; k < NCHUNK / 4; k++) {
        int c = q + 4 * k;
        float l = g_l[c * NQ + h];
        if (l > 0.f) {
            L += l;
            acc += g_part[(c * NQ + h) * HD + d];
        }
    }
    __shared__ float sacc[4][64];
    __shared__ float sL[4][64];
    sacc[q][dl] = acc;
    sL[q][dl]   = L;
    __syncthreads();
    if (q == 0) {
        acc = sacc[0][dl] + sacc[1][dl] + sacc[2][dl] + sacc[3][dl];
        L   = sL[0][dl] + sL[1][dl] + sL[2][dl] + sL[3][dl];
        g_attn[h * HD + d] = acc / L;
    }
}

// ---------------- launch ----------------------------------------------------
extern "C" void kernel_launch(void* const* d_in, const int* in_sizes, int n_in,
                              void* d_out, int out_size) {
    const float* hs   = (const float*)d_in[0];   // hidden_states (2048)
    const float* cosv = (const float*)d_in[1];   // cos (256)
    const float* sinv = (const float*)d_in[2];   // sin (256)
    const int*   kvix = (const int*)  d_in[3];   // kv_write_indices (1)
    const float* kc   = (const float*)d_in[4];   // k_cache
    const float* vc   = (const float*)d_in[5];   // v_cache
    const float* mask = (const float*)d_in[6];   // mask (8192)
    const float* qkvw = (const float*)d_in[7];   // qkv_w (2560x2048)
    const float* ow   = (const float*)d_in[8];   // o_w   (2048x2048)
    const float* qnw  = (const float*)d_in[9];   // q_norm_w (256)
    const float* knw  = (const float*)d_in[10];  // k_norm_w (256)
    float* out = (float*)d_out;

    void* p_qkv = nullptr;
    void* p_attn = nullptr;
    cudaGetSymbolAddress(&p_qkv, g_qkv);
    cudaGetSymbolAddress(&p_attn, g_attn);

    gemv_kernel<<<QKV_ROWS / 2, 256>>>(qkvw, hs, (float*)p_qkv);
    fused_attn_kernel<<<NCHUNK, 256>>>(kc, vc, mask, cosv, sinv, qnw, knw, kvix);
    combine_kernel<<<dim3(NQ, 4), 256>>>();
    gemv_kernel<<<HIDDEN / 2, 256>>>(ow, (const float*)p_attn, out);
}